// round 15
// baseline (speedup 1.0000x reference)
#include <cuda_runtime.h>
#include <math.h>

#define BB 8
#define TT 1024
#define DD 1024
#define HH 16
#define D3 3072

// ---------------- scratch (static device arrays; no runtime allocation) ----------------
__device__ float g_qkv[25165824];   // [B,T,3D]
__device__ float g_S  [134217728];  // [B,H,T,T] attention scores
__device__ float g_ctx[8388608];    // [B,T,D]
__device__ float g_A  [8388608];    // [B,T,D]   attention output
__device__ float g_Ht [8192];       // transposed hidden state [d][b]
__device__ float g_H1t[8192];       // transposed post-GRU state [d][b]
__device__ unsigned g_tagH [2048];  // tag slots, 32B padded
__device__ unsigned g_tagH1[2048];

// ---------------- packed f32x2 helpers ----------------
__device__ __forceinline__ void fma2(unsigned long long& d, unsigned long long a,
                                     unsigned long long b, unsigned long long c)
{
    asm("fma.rn.f32x2 %0, %1, %2, %3;" : "=l"(d) : "l"(a), "l"(b), "l"(c));
}
__device__ __forceinline__ unsigned long long add2(unsigned long long a, unsigned long long b)
{
    unsigned long long d;
    asm("add.rn.f32x2 %0, %1, %2;" : "=l"(d) : "l"(a), "l"(b));
    return d;
}
__device__ __forceinline__ unsigned long long pack2(float x)
{
    unsigned long long d; unsigned u = __float_as_uint(x);
    asm("mov.b64 %0, {%1, %2};" : "=l"(d) : "r"(u), "r"(u));
    return d;
}
__device__ __forceinline__ void unpack2(unsigned long long v, float& lo, float& hi)
{
    unsigned a, b;
    asm("mov.b64 {%0, %1}, %2;" : "=r"(a), "=r"(b) : "l"(v));
    lo = __uint_as_float(a); hi = __uint_as_float(b);
}
__device__ __forceinline__ float fsig(float x)
{
    return __fdividef(1.f, 1.f + __expf(-x));
}
__device__ __forceinline__ float ftanh(float x)
{
    return 1.f - __fdividef(2.f, __expf(2.f * x) + 1.f);
}

// ---------------- 128x128 tiled SGEMM (f32x2 core): C = scale*(A@op(B)) + bias ----------------
#define GEMM_LOAD(buf, kofs) do {                                               \
    float4 va = *(const float4*)&A[(long long)ar*lda + (kofs) + aq];            \
    As[buf][aq+0][ar]=va.x; As[buf][aq+1][ar]=va.y;                             \
    As[buf][aq+2][ar]=va.z; As[buf][aq+3][ar]=va.w;                             \
    if constexpr (TB) {                                                         \
      if (TN == 128 || t < 128) {                                               \
        float4 vb = *(const float4*)&Bp[(n0 + ar)*ldb + (kofs) + aq];           \
        Bs[buf][aq+0][ar]=vb.x; Bs[buf][aq+1][ar]=vb.y;                         \
        Bs[buf][aq+2][ar]=vb.z; Bs[buf][aq+3][ar]=vb.w;                         \
      }                                                                         \
    } else {                                                                    \
      if constexpr (TN == 128) {                                                \
        int kk = t >> 5, nn = (t & 31) * 4;                                     \
        *(float4*)&Bs[buf][kk][nn] =                                            \
            *(const float4*)&Bp[(long long)((kofs)+kk)*ldb + n0 + nn];          \
      } else {                                                                  \
        if (t < 128) { int kk = t >> 4, nn = (t & 15) * 4;                      \
          *(float4*)&Bs[buf][kk][nn] =                                          \
              *(const float4*)&Bp[(long long)((kofs)+kk)*ldb + n0 + nn]; }      \
      }                                                                         \
    }                                                                           \
  } while (0)

template<int TN, bool TB>
__global__ __launch_bounds__(256) void gemm_k(
    const float* __restrict__ A0, int lda, long long sA1, long long sA2,
    const float* __restrict__ B0, int ldb, long long sB1, long long sB2,
    float* __restrict__ C0, int ldc, long long sC1, long long sC2,
    int K, int Z2, const float* __restrict__ bias, float scale)
{
    constexpr int NJ = TN / 16;     // 8 or 4
    constexpr int NP = NJ / 2;      // accumulator pairs: 4 or 2
    int z  = blockIdx.z;
    int z1 = z / Z2, z2 = z - z1 * Z2;
    const float* A  = A0 + z1 * sA1 + z2 * sA2 + (long long)blockIdx.y * 128 * lda;
    const float* Bp = B0 + z1 * sB1 + z2 * sB2;
    float*       C  = C0 + z1 * sC1 + z2 * sC2 + (long long)blockIdx.y * 128 * ldc
                         + (long long)blockIdx.x * TN;
    long long n0 = (long long)blockIdx.x * TN;

    __shared__ float As[2][8][128];
    __shared__ float Bs[2][8][TN];
    int t = threadIdx.x, tx = t & 15, ty = t >> 4;
    int ar = t >> 1, aq = (t & 1) * 4;

    unsigned long long acc2[8][NP];
    #pragma unroll
    for (int i = 0; i < 8; i++)
        #pragma unroll
        for (int j = 0; j < NP; j++) acc2[i][j] = 0ull;

    int nk = K >> 3;
    GEMM_LOAD(0, 0);
    __syncthreads();

    for (int kt = 0; kt < nk; kt++) {
        int cb = kt & 1, nb = cb ^ 1;
        if (kt + 1 < nk) { GEMM_LOAD(nb, (kt + 1) << 3); }
        #pragma unroll
        for (int kk = 0; kk < 8; kk++) {
            float4 a0 = *(const float4*)&As[cb][kk][ty * 4];
            float4 a1 = *(const float4*)&As[cb][kk][ty * 4 + 64];
            ulonglong2 b01 = *(const ulonglong2*)&Bs[cb][kk][tx * 4];
            float av[8] = {a0.x,a0.y,a0.z,a0.w,a1.x,a1.y,a1.z,a1.w};
            if constexpr (NP == 4) {
                ulonglong2 b23 = *(const ulonglong2*)&Bs[cb][kk][tx * 4 + 64];
                #pragma unroll
                for (int i = 0; i < 8; i++) {
                    unsigned long long pa = pack2(av[i]);
                    fma2(acc2[i][0], b01.x, pa, acc2[i][0]);
                    fma2(acc2[i][1], b01.y, pa, acc2[i][1]);
                    fma2(acc2[i][2], b23.x, pa, acc2[i][2]);
                    fma2(acc2[i][3], b23.y, pa, acc2[i][3]);
                }
            } else {
                #pragma unroll
                for (int i = 0; i < 8; i++) {
                    unsigned long long pa = pack2(av[i]);
                    fma2(acc2[i][0], b01.x, pa, acc2[i][0]);
                    fma2(acc2[i][1], b01.y, pa, acc2[i][1]);
                }
            }
        }
        __syncthreads();
    }

    #pragma unroll
    for (int i = 0; i < 8; i++) {
        int row = (i < 4) ? (ty * 4 + i) : (64 + ty * 4 + (i - 4));
        #pragma unroll
        for (int jh = 0; jh < NP / 2; jh++) {
            int col = tx * 4 + jh * 64;
            float4 v;
            unpack2(acc2[i][jh*2+0], v.x, v.y);
            unpack2(acc2[i][jh*2+1], v.z, v.w);
            v.x *= scale; v.y *= scale; v.z *= scale; v.w *= scale;
            if (bias) {
                v.x += bias[n0+col]; v.y += bias[n0+col+1];
                v.z += bias[n0+col+2]; v.w += bias[n0+col+3];
            }
            *(float4*)&C[(long long)row * ldc + col] = v;
        }
    }
}

// ---------------- row softmax over 1024 columns ----------------
__global__ __launch_bounds__(256) void softmax_k(float* __restrict__ S)
{
    long long row = blockIdx.x;
    float* p = S + row * (long long)TT;
    int t = threadIdx.x;
    float v0 = p[t], v1 = p[t + 256], v2 = p[t + 512], v3 = p[t + 768];
    float m = fmaxf(fmaxf(v0, v1), fmaxf(v2, v3));
    __shared__ float sredm[8];
    __shared__ float sreds[8];
    #pragma unroll
    for (int o = 16; o; o >>= 1) m = fmaxf(m, __shfl_xor_sync(0xffffffffu, m, o));
    if ((t & 31) == 0) sredm[t >> 5] = m;
    __syncthreads();
    m = fmaxf(fmaxf(fmaxf(sredm[0], sredm[1]), fmaxf(sredm[2], sredm[3])),
              fmaxf(fmaxf(sredm[4], sredm[5]), fmaxf(sredm[6], sredm[7])));
    v0 = expf(v0 - m); v1 = expf(v1 - m); v2 = expf(v2 - m); v3 = expf(v3 - m);
    float s = (v0 + v1) + (v2 + v3);
    #pragma unroll
    for (int o = 16; o; o >>= 1) s += __shfl_xor_sync(0xffffffffu, s, o);
    if ((t & 31) == 0) sreds[t >> 5] = s;
    __syncthreads();
    s = ((sreds[0] + sreds[1]) + (sreds[2] + sreds[3]))
      + ((sreds[4] + sreds[5]) + (sreds[6] + sreds[7]));
    float inv = 1.f / s;
    p[t] = v0 * inv; p[t + 256] = v1 * inv; p[t + 512] = v2 * inv; p[t + 768] = v3 * inv;
}

// ---------------- state / tag reset ----------------
__global__ void reset_k()
{
    int i = blockIdx.x * blockDim.x + threadIdx.x;
    if (i < BB * DD) { g_Ht[i] = 0.f; g_H1t[i] = 0.f; }
    if (i < 2048) { g_tagH[i] = 0u; g_tagH1[i] = 0u; }
}

// ---------------- persistent recurrent kernel (per-block tagged dataflow) ----------------
#define GBLK 128
#define PTH  512

// Poll 8 producer tags (32B-padded) until all reach tgt.
__device__ __forceinline__ void wait_tags8(const unsigned* tags, int w, unsigned tgt)
{
    int lane = threadIdx.x & 31;
    const unsigned* p = tags + (((w << 3) + (lane & 7)) << 3);
    unsigned v; int miss = 0;
    while (true) {
        asm volatile("ld.acquire.gpu.u32 %0, [%1];" : "=r"(v) : "l"(p) : "memory");
        if (__all_sync(0xffffffffu, v >= tgt)) break;
        if (++miss > 3) __nanosleep(30);
    }
}

// On-the-fly GI/AG slice: one row r of W dotted with 8 batch rows of operand.
// Lane layout per warp: row_sub = lane>>4 (2 rows), kc = lane&15 (k-interleaved).
// acc[b] holds (even-k, odd-k) partial pair; reduced over kc by shfl; kc==0 writes.
__device__ __forceinline__ void gi_burst(
    int kc, const float* __restrict__ base /* operand + tokN*DD */,
    const float* __restrict__ wp /* weight row */,
    unsigned long long* __restrict__ dst /* smem [8] */)
{
    unsigned long long acc[8] = {0,0,0,0,0,0,0,0};
    #pragma unroll 2
    for (int i = 0; i < 16; i++) {
        int k = i * 64 + kc * 4;
        ulonglong2 wq = __ldg((const ulonglong2*)(wp + k));
        #pragma unroll
        for (int b = 0; b < 8; b++) {
            ulonglong2 xq = __ldg((const ulonglong2*)(base + (size_t)b * TT * DD + k));
            fma2(acc[b], xq.x, wq.x, acc[b]);
            fma2(acc[b], xq.y, wq.y, acc[b]);
        }
    }
    #pragma unroll
    for (int o = 1; o <= 8; o <<= 1)
        #pragma unroll
        for (int b = 0; b < 8; b++)
            acc[b] = add2(acc[b], __shfl_xor_sync(0xffffffffu, acc[b], o));
    if (kc == 0) {
        #pragma unroll
        for (int b = 0; b < 8; b++) dst[b] = acc[b];
    }
}

__global__ __launch_bounds__(PTH, 1) void recur_k(
    const float* __restrict__ w_hh, const float* __restrict__ b_hh,
    const float* __restrict__ gate_w,
    const float* __restrict__ xg, const float* __restrict__ w_ih,
    const float* __restrict__ b_ih, const float* __restrict__ gb,
    float* __restrict__ out)
{
    __shared__ unsigned long long part[16 * 96];   // per-warp partials
    __shared__ unsigned long long ghs[96];         // phase1 reduced (u64 pairs)
    __shared__ unsigned long long g2s[32];         // phase2 reduced
    __shared__ unsigned long long giS[2][32][8];   // GI(24 rows)+AG(8 rows) per token, ping-pong
    __shared__ float bs1[24];                      // b_hh
    __shared__ float bihS[24];                     // b_ih
    __shared__ float gbS[8];                       // gate_b

    int t = threadIdx.x, g = blockIdx.x;
    int d0 = g * 8;
    int w = t >> 5, lane = t & 31;

    int rsub = lane >> 2, kq1 = lane & 3;   // phase1 matvec roles
    int rg2 = lane >> 3, kq2 = lane & 7;    // phase2 matvec roles
    // elementwise roles on the TOP warps (highest arbiter priority)
    int te = t - 448;                       // valid for t >= 448
    int ed = te >> 3, eb = te & 7;
    int dg = d0 + (ed & 7);
    // gi-burst roles (warps 0-7)
    int brs = lane >> 4, bkc = lane & 15;

    // ---- weights resident in registers ----
    float w1[3][16];
    #pragma unroll
    for (int q = 0; q < 3; q++) {
        int rho = rsub * 3 + q;
        const float* wr = w_hh + (size_t)((rho >> 3) * DD + d0 + (rho & 7)) * DD
                        + w * 64 + kq1;
        #pragma unroll
        for (int i = 0; i < 16; i++) w1[q][i] = wr[4 * i];
    }
    float w2[2][8];
    #pragma unroll
    for (int r = 0; r < 2; r++) {
        const float* wr = gate_w + (size_t)(d0 + rg2 * 2 + r) * (2 * DD)
                        + w * 64 + kq2;
        #pragma unroll
        for (int i = 0; i < 8; i++) w2[r][i] = wr[8 * i];
    }
    if (t < 24) bs1[t] = b_hh[(t >> 3) * DD + d0 + (t & 7)];
    if (t >= 32 && t < 56) { int i = t - 32; bihS[i] = b_ih[(i >> 3) * DD + d0 + (i & 7)]; }
    if (t >= 64 && t < 72) gbS[t - 64] = gb[d0 + (t - 64)];
    __syncthreads();

    // ---- prologue: GI/AG for token 0 into parity 0 ----
    if (w < 8) {
        #pragma unroll 1
        for (int bu = 0; bu < 2; bu++) {
            int r = 4 * w + 2 * bu + brs;
            const float* base; const float* wp;
            if (r < 24) { int c = r >> 3, j = r & 7;
                wp = w_ih + (size_t)(c * DD + d0 + j) * DD;
                base = xg; }
            else { int j = r - 24;
                wp = gate_w + (size_t)(d0 + j) * (2 * DD) + DD;
                base = g_A; }
            gi_burst(bkc, base, wp, &giS[0][r][0]);
        }
    }
    __syncthreads();

    unsigned e = 0;
    float h_own = 0.f, h1_own = 0.f;

    const ulonglong2* Hg  = (const ulonglong2*)g_Ht;
    const ulonglong2* H1g = (const ulonglong2*)g_H1t;

    // per-token operands held by elem threads
    float girC = 0, gizC = 0, ginC = 0, avC = 0, agvC = 0;
    float avN = 0;
    if (t >= 448) {
        avC = __ldg(&g_A[((size_t)(eb * TT)) * DD + dg]);
    }

    for (int tok = 0; tok < TT; tok++) {
        #pragma unroll 1
        for (int s = 0; s < 4; s++) {
            // ---- phase 1: gh = W_hh . h ----
            {
                wait_tags8(g_tagH, w, e);
                unsigned long long acc[12];
                #pragma unroll
                for (int j = 0; j < 12; j++) acc[j] = 0ull;
                int kb = w * 64 + kq1;
                #pragma unroll
                for (int i = 0; i < 16; i++) {
                    int ii = (i + g) & 15;                 // block-staggered order
                    int k = kb + 4 * ii;
                    ulonglong2 p0 = __ldcg(&Hg[k * 2]);
                    ulonglong2 p1 = __ldcg(&Hg[k * 2 + 1]);
                    #pragma unroll
                    for (int q = 0; q < 3; q++) {
                        unsigned long long wd = pack2(w1[q][ii]);
                        fma2(acc[q*4+0], p0.x, wd, acc[q*4+0]);
                        fma2(acc[q*4+1], p0.y, wd, acc[q*4+1]);
                        fma2(acc[q*4+2], p1.x, wd, acc[q*4+2]);
                        fma2(acc[q*4+3], p1.y, wd, acc[q*4+3]);
                    }
                }
                #pragma unroll
                for (int o = 1; o <= 2; o <<= 1)
                    #pragma unroll
                    for (int j = 0; j < 12; j++)
                        acc[j] = add2(acc[j], __shfl_xor_sync(0xffffffffu, acc[j], o));
                if (kq1 == 0) {
                    #pragma unroll
                    for (int j = 0; j < 12; j++) part[w * 96 + rsub * 12 + j] = acc[j];
                }
            }
            __syncthreads();
            if (t >= 416) {                                // warps 13-15 reduce
                int tr = t - 416;
                unsigned long long d = part[tr];
                #pragma unroll
                for (int wv = 1; wv < 16; wv++) d = add2(d, part[wv * 96 + tr]);
                ghs[tr] = d;
            }
            __syncthreads();

            // ---- GRU elementwise -> publish h1 (top warps) ----
            if (t >= 448) {
                if (s == 0) {                              // token operands from smem
                    int par = tok & 1;
                    float lo, hi;
                    unpack2(giS[par][ed][eb], lo, hi);        girC = lo + hi + bihS[ed];
                    unpack2(giS[par][8 + ed][eb], lo, hi);    gizC = lo + hi + bihS[8 + ed];
                    unpack2(giS[par][16 + ed][eb], lo, hi);   ginC = lo + hi + bihS[16 + ed];
                    unpack2(giS[par][24 + ed][eb], lo, hi);   agvC = lo + hi + gbS[ed];
                }
                const float* ghf = (const float*)ghs;
                float gh[3];
                #pragma unroll
                for (int c = 0; c < 3; c++) {
                    int rho = c * 8 + ed;
                    int o = (rho / 3) * 12 + (rho % 3) * 4 + (eb >> 1);
                    gh[c] = ghf[o * 2 + (eb & 1)] + bs1[rho];
                }
                float rr = fsig(girC + gh[0]);
                float zz = fsig(gizC + gh[1]);
                float nn = ftanh(ginC + rr * gh[2]);
                h1_own = (1.f - zz) * nn + zz * h_own;
                __stcg(&g_H1t[dg * 8 + eb], h1_own);
                __syncwarp();
                if (lane == 0) {
                    unsigned tg = e + 1;
                    asm volatile("st.release.gpu.u32 [%0], %1;"
                                 :: "l"(&g_tagH1[(g * 2 + (w - 14)) * 8]), "r"(tg) : "memory");
                }
                if (s == 0 && tok + 1 < TT) {
                    avN = __ldg(&g_A[((size_t)(eb * TT + tok + 1)) * DD + dg]);
                }
            }

            // ---- phase 2: gate dot ----
            {
                wait_tags8(g_tagH1, w, e + 1);
                unsigned long long a2[8];
                #pragma unroll
                for (int j = 0; j < 8; j++) a2[j] = 0ull;
                int kb = w * 64 + kq2;
                #pragma unroll
                for (int i = 0; i < 8; i++) {
                    int ii = (i + g) & 7;                  // block-staggered order
                    int k = kb + 8 * ii;
                    ulonglong2 p0 = __ldcg(&H1g[k * 2]);
                    ulonglong2 p1 = __ldcg(&H1g[k * 2 + 1]);
                    #pragma unroll
                    for (int r = 0; r < 2; r++) {
                        unsigned long long wd = pack2(w2[r][ii]);
                        fma2(a2[r*4+0], p0.x, wd, a2[r*4+0]);
                        fma2(a2[r*4+1], p0.y, wd, a2[r*4+1]);
                        fma2(a2[r*4+2], p1.x, wd, a2[r*4+2]);
                        fma2(a2[r*4+3], p1.y, wd, a2[r*4+3]);
                    }
                }
                #pragma unroll
                for (int o = 1; o <= 4; o <<= 1)
                    #pragma unroll
                    for (int j = 0; j < 8; j++)
                        a2[j] = add2(a2[j], __shfl_xor_sync(0xffffffffu, a2[j], o));
                if (kq2 == 0) {
                    #pragma unroll
                    for (int j = 0; j < 8; j++) part[w * 32 + rg2 * 8 + j] = a2[j];
                }
            }
            __syncthreads();
            if (t >= 480) {                                // warp 15 reduces
                int tr = t - 480;
                unsigned long long d = part[tr];
                #pragma unroll
                for (int wv = 1; wv < 16; wv++) d = add2(d, part[wv * 32 + tr]);
                g2s[tr] = d;
            }
            __syncthreads();

            // ---- gate elementwise -> publish new h (+ output on last sub-step) ----
            if (t >= 448) {
                const float* g2f = (const float*)g2s;
                float dot = g2f[ed * 8 + eb];
                float gv  = fsig(dot + agvC);
                h_own = gv * h1_own + (1.f - gv) * avC;
                __stcg(&g_Ht[dg * 8 + eb], h_own);
                if (s == 3) out[((size_t)(eb * TT + tok)) * DD + dg] = h_own;
                __syncwarp();
                if (lane == 0) {
                    unsigned tg = e + 1;
                    asm volatile("st.release.gpu.u32 [%0], %1;"
                                 :: "l"(&g_tagH[(g * 2 + (w - 14)) * 8]), "r"(tg) : "memory");
                }
            } else if (w < 8 && s < 2 && tok + 1 < TT) {
                // ---- hidden work: next token's GI/AG slice (2 rows/warp/burst) ----
                int r = 4 * w + 2 * s + brs;
                const float* base; const float* wp;
                if (r < 24) { int c = r >> 3, j = r & 7;
                    wp = w_ih + (size_t)(c * DD + d0 + j) * DD;
                    base = xg + (size_t)(tok + 1) * DD; }
                else { int j = r - 24;
                    wp = gate_w + (size_t)(d0 + j) * (2 * DD) + DD;
                    base = g_A + (size_t)(tok + 1) * DD; }
                gi_burst(bkc, base, wp, &giS[(tok + 1) & 1][r][0]);
            }
            e++;
        }
        avC = avN;
    }
}

// ---------------- launch ----------------
extern "C" void kernel_launch(void* const* d_in, const int* in_sizes, int n_in,
                              void* d_out, int out_size)
{
    (void)in_sizes; (void)n_in; (void)out_size;
    const float* x   = (const float*)d_in[0];
    const float* ipw = (const float*)d_in[1];
    const float* ipb = (const float*)d_in[2];
    const float* opw = (const float*)d_in[3];
    const float* opb = (const float*)d_in[4];
    const float* wih = (const float*)d_in[5];
    const float* whh = (const float*)d_in[6];
    const float* bih = (const float*)d_in[7];
    const float* bhh = (const float*)d_in[8];
    const float* gw  = (const float*)d_in[9];
    const float* gb  = (const float*)d_in[10];
    float* out = (float*)d_out;

    float *qkv, *S, *ctx, *A;
    cudaGetSymbolAddress((void**)&qkv, g_qkv);
    cudaGetSymbolAddress((void**)&S,   g_S);
    cudaGetSymbolAddress((void**)&ctx, g_ctx);
    cudaGetSymbolAddress((void**)&A,   g_A);

    dim3 blk(256);
    // 1) qkv = x @ in_proj^T + b            [8192,3072]
    gemm_k<128,true><<<dim3(D3/128, (BB*TT)/128, 1), blk>>>(
        x, DD, 0, 0, ipw, DD, 0, 0, qkv, D3, 0, 0, DD, 1, ipb, 1.f);
    // 2) scores S[b,h] = Q K^T / 8          batched 128x [1024,1024], K=64
    gemm_k<128,true><<<dim3(TT/128, TT/128, BB*HH), blk>>>(
        qkv,      D3, (long long)TT*D3, 64,
        qkv + DD, D3, (long long)TT*D3, 64,
        S, TT, (long long)HH*TT*TT, (long long)TT*TT,
        64, HH, nullptr, 0.125f);
    // 3) softmax rows
    softmax_k<<<BB*HH*TT, 256>>>(S);
    // 4) ctx[b,h] = S @ V                   batched 128x [1024,64], K=1024
    gemm_k<64,false><<<dim3(1, TT/128, BB*HH), blk>>>(
        S, TT, (long long)HH*TT*TT, (long long)TT*TT,
        qkv + 2*DD, D3, (long long)TT*D3, 64,
        ctx, DD, (long long)TT*DD, 64,
        TT, HH, nullptr, 1.f);
    // 5) A = ctx @ out_proj^T + b           [8192,1024]
    gemm_k<128,true><<<dim3(DD/128, (BB*TT)/128, 1), blk>>>(
        ctx, DD, 0, 0, opw, DD, 0, 0, A, DD, 0, 0, DD, 1, opb, 1.f);
    // 6) reset h buffers + tags (deterministic across graph replays)
    reset_k<<<32, 256>>>();
    // 7) persistent recurrence; GI and AG computed on the fly in idle warps
    recur_k<<<GBLK, PTH>>>(whh, bhh, gw, x, wih, bih, gb, out);
}

// round 17
// speedup vs baseline: 1.3302x; 1.3302x over previous
#include <cuda_runtime.h>
#include <math.h>

#define BB 8
#define TT 1024
#define DD 1024
#define HH 16
#define D3 3072

// ---------------- scratch (static device arrays; no runtime allocation) ----------------
__device__ float g_qkv[25165824];   // [B,T,3D]
__device__ float g_GI [25165824];   // [B,T,3D]  x@w_ih^T + b_ih (produced in-flight)
__device__ float g_S  [134217728];  // [B,H,T,T] attention scores
__device__ float g_ctx[8388608];    // [B,T,D]
__device__ float g_A  [8388608];    // [B,T,D]   attention output
__device__ float g_AG [8388608];    // [B,T,D]   a-part of gate preact (incl. gate_b)
__device__ float g_Ht [8192];       // transposed hidden state [d][b]
__device__ float g_H1t[8192];       // transposed post-GRU state [d][b]
__device__ unsigned g_tagH [2048];  // tag slots, 32B padded
__device__ unsigned g_tagH1[2048];
__device__ unsigned g_giProg[32];   // per-32-token-chunk GI completion counters

// ---------------- packed f32x2 helpers ----------------
__device__ __forceinline__ void fma2(unsigned long long& d, unsigned long long a,
                                     unsigned long long b, unsigned long long c)
{
    asm("fma.rn.f32x2 %0, %1, %2, %3;" : "=l"(d) : "l"(a), "l"(b), "l"(c));
}
__device__ __forceinline__ unsigned long long add2(unsigned long long a, unsigned long long b)
{
    unsigned long long d;
    asm("add.rn.f32x2 %0, %1, %2;" : "=l"(d) : "l"(a), "l"(b));
    return d;
}
__device__ __forceinline__ unsigned long long pack2(float x)
{
    unsigned long long d; unsigned u = __float_as_uint(x);
    asm("mov.b64 %0, {%1, %2};" : "=l"(d) : "r"(u), "r"(u));
    return d;
}
__device__ __forceinline__ void unpack2(unsigned long long v, float& lo, float& hi)
{
    unsigned a, b;
    asm("mov.b64 {%0, %1}, %2;" : "=r"(a), "=r"(b) : "l"(v));
    lo = __uint_as_float(a); hi = __uint_as_float(b);
}
__device__ __forceinline__ float fsig(float x)
{
    return __fdividef(1.f, 1.f + __expf(-x));
}
__device__ __forceinline__ float ftanh(float x)
{
    return 1.f - __fdividef(2.f, __expf(2.f * x) + 1.f);
}

// ---------------- 128x128 tiled SGEMM (f32x2 core): C = scale*(A@op(B)) + bias ----------------
#define GEMM_LOAD(buf, kofs) do {                                               \
    float4 va = *(const float4*)&A[(long long)ar*lda + (kofs) + aq];            \
    As[buf][aq+0][ar]=va.x; As[buf][aq+1][ar]=va.y;                             \
    As[buf][aq+2][ar]=va.z; As[buf][aq+3][ar]=va.w;                             \
    if constexpr (TB) {                                                         \
      if (TN == 128 || t < 128) {                                               \
        float4 vb = *(const float4*)&Bp[(n0 + ar)*ldb + (kofs) + aq];           \
        Bs[buf][aq+0][ar]=vb.x; Bs[buf][aq+1][ar]=vb.y;                         \
        Bs[buf][aq+2][ar]=vb.z; Bs[buf][aq+3][ar]=vb.w;                         \
      }                                                                         \
    } else {                                                                    \
      if constexpr (TN == 128) {                                                \
        int kk = t >> 5, nn = (t & 31) * 4;                                     \
        *(float4*)&Bs[buf][kk][nn] =                                            \
            *(const float4*)&Bp[(long long)((kofs)+kk)*ldb + n0 + nn];          \
      } else {                                                                  \
        if (t < 128) { int kk = t >> 4, nn = (t & 15) * 4;                      \
          *(float4*)&Bs[buf][kk][nn] =                                          \
              *(const float4*)&Bp[(long long)((kofs)+kk)*ldb + n0 + nn]; }      \
      }                                                                         \
    }                                                                           \
  } while (0)

template<int TN, bool TB>
__global__ __launch_bounds__(256) void gemm_k(
    const float* __restrict__ A0, int lda, long long sA1, long long sA2,
    const float* __restrict__ B0, int ldb, long long sB1, long long sB2,
    float* __restrict__ C0, int ldc, long long sC1, long long sC2,
    int K, int Z2, const float* __restrict__ bias, float scale)
{
    constexpr int NJ = TN / 16;     // 8 or 4
    constexpr int NP = NJ / 2;      // accumulator pairs: 4 or 2
    int z  = blockIdx.z;
    int z1 = z / Z2, z2 = z - z1 * Z2;
    const float* A  = A0 + z1 * sA1 + z2 * sA2 + (long long)blockIdx.y * 128 * lda;
    const float* Bp = B0 + z1 * sB1 + z2 * sB2;
    float*       C  = C0 + z1 * sC1 + z2 * sC2 + (long long)blockIdx.y * 128 * ldc
                         + (long long)blockIdx.x * TN;
    long long n0 = (long long)blockIdx.x * TN;

    __shared__ float As[2][8][128];
    __shared__ float Bs[2][8][TN];
    int t = threadIdx.x, tx = t & 15, ty = t >> 4;
    int ar = t >> 1, aq = (t & 1) * 4;

    unsigned long long acc2[8][NP];
    #pragma unroll
    for (int i = 0; i < 8; i++)
        #pragma unroll
        for (int j = 0; j < NP; j++) acc2[i][j] = 0ull;

    int nk = K >> 3;
    GEMM_LOAD(0, 0);
    __syncthreads();

    for (int kt = 0; kt < nk; kt++) {
        int cb = kt & 1, nb = cb ^ 1;
        if (kt + 1 < nk) { GEMM_LOAD(nb, (kt + 1) << 3); }
        #pragma unroll
        for (int kk = 0; kk < 8; kk++) {
            float4 a0 = *(const float4*)&As[cb][kk][ty * 4];
            float4 a1 = *(const float4*)&As[cb][kk][ty * 4 + 64];
            ulonglong2 b01 = *(const ulonglong2*)&Bs[cb][kk][tx * 4];
            float av[8] = {a0.x,a0.y,a0.z,a0.w,a1.x,a1.y,a1.z,a1.w};
            if constexpr (NP == 4) {
                ulonglong2 b23 = *(const ulonglong2*)&Bs[cb][kk][tx * 4 + 64];
                #pragma unroll
                for (int i = 0; i < 8; i++) {
                    unsigned long long pa = pack2(av[i]);
                    fma2(acc2[i][0], b01.x, pa, acc2[i][0]);
                    fma2(acc2[i][1], b01.y, pa, acc2[i][1]);
                    fma2(acc2[i][2], b23.x, pa, acc2[i][2]);
                    fma2(acc2[i][3], b23.y, pa, acc2[i][3]);
                }
            } else {
                #pragma unroll
                for (int i = 0; i < 8; i++) {
                    unsigned long long pa = pack2(av[i]);
                    fma2(acc2[i][0], b01.x, pa, acc2[i][0]);
                    fma2(acc2[i][1], b01.y, pa, acc2[i][1]);
                }
            }
        }
        __syncthreads();
    }

    #pragma unroll
    for (int i = 0; i < 8; i++) {
        int row = (i < 4) ? (ty * 4 + i) : (64 + ty * 4 + (i - 4));
        #pragma unroll
        for (int jh = 0; jh < NP / 2; jh++) {
            int col = tx * 4 + jh * 64;
            float4 v;
            unpack2(acc2[i][jh*2+0], v.x, v.y);
            unpack2(acc2[i][jh*2+1], v.z, v.w);
            v.x *= scale; v.y *= scale; v.z *= scale; v.w *= scale;
            if (bias) {
                v.x += bias[n0+col]; v.y += bias[n0+col+1];
                v.z += bias[n0+col+2]; v.w += bias[n0+col+3];
            }
            *(float4*)&C[(long long)row * ldc + col] = v;
        }
    }
}

// ---------------- row softmax over 1024 columns ----------------
__global__ __launch_bounds__(256) void softmax_k(float* __restrict__ S)
{
    long long row = blockIdx.x;
    float* p = S + row * (long long)TT;
    int t = threadIdx.x;
    float v0 = p[t], v1 = p[t + 256], v2 = p[t + 512], v3 = p[t + 768];
    float m = fmaxf(fmaxf(v0, v1), fmaxf(v2, v3));
    __shared__ float sredm[8];
    __shared__ float sreds[8];
    #pragma unroll
    for (int o = 16; o; o >>= 1) m = fmaxf(m, __shfl_xor_sync(0xffffffffu, m, o));
    if ((t & 31) == 0) sredm[t >> 5] = m;
    __syncthreads();
    m = fmaxf(fmaxf(fmaxf(sredm[0], sredm[1]), fmaxf(sredm[2], sredm[3])),
              fmaxf(fmaxf(sredm[4], sredm[5]), fmaxf(sredm[6], sredm[7])));
    v0 = expf(v0 - m); v1 = expf(v1 - m); v2 = expf(v2 - m); v3 = expf(v3 - m);
    float s = (v0 + v1) + (v2 + v3);
    #pragma unroll
    for (int o = 16; o; o >>= 1) s += __shfl_xor_sync(0xffffffffu, s, o);
    if ((t & 31) == 0) sreds[t >> 5] = s;
    __syncthreads();
    s = ((sreds[0] + sreds[1]) + (sreds[2] + sreds[3]))
      + ((sreds[4] + sreds[5]) + (sreds[6] + sreds[7]));
    float inv = 1.f / s;
    p[t] = v0 * inv; p[t + 256] = v1 * inv; p[t + 512] = v2 * inv; p[t + 768] = v3 * inv;
}

// ---------------- state / tag / progress reset ----------------
__global__ void reset_k()
{
    int i = blockIdx.x * blockDim.x + threadIdx.x;
    if (i < BB * DD) { g_Ht[i] = 0.f; g_H1t[i] = 0.f; }
    if (i < 2048) { g_tagH[i] = 0u; g_tagH1[i] = 0u; }
    if (i < 32) g_giProg[i] = 0u;
}

// ---------------- fused persistent kernel: recur (blocks 0-127) + GI producer (128-143) ----
#define GBLK 128
#define NPROD 16
#define PTH  512

// Poll 8 producer tags (32B-padded) until all reach tgt.
__device__ __forceinline__ void wait_tags8(const unsigned* tags, int w, unsigned tgt)
{
    int lane = threadIdx.x & 31;
    const unsigned* p = tags + (((w << 3) + (lane & 7)) << 3);
    unsigned v; int miss = 0;
    while (true) {
        asm volatile("ld.acquire.gpu.u32 %0, [%1];" : "=r"(v) : "l"(p) : "memory");
        if (__all_sync(0xffffffffu, v >= tgt)) break;
        if (++miss > 3) __nanosleep(30);
    }
}

// Wait until GI chunk c is fully produced (NPROD producer blocks arrived).
__device__ __forceinline__ void wait_gi(int c)
{
    const unsigned* p = &g_giProg[c];
    unsigned v; int miss = 0;
    while (true) {
        asm volatile("ld.acquire.gpu.u32 %0, [%1];" : "=r"(v) : "l"(p) : "memory");
        if (v >= NPROD) break;
        if (++miss > 3) __nanosleep(100);
    }
}

__global__ __launch_bounds__(PTH, 1) void recur_k(
    const float* __restrict__ w_hh, const float* __restrict__ b_hh,
    const float* __restrict__ gate_w,
    const float* __restrict__ xg, const float* __restrict__ w_ih,
    const float* __restrict__ b_ih,
    float* __restrict__ out)
{
    __shared__ unsigned long long part[16 * 96];   // per-warp partials (recur)
    __shared__ unsigned long long ghs[96];
    __shared__ unsigned long long g2s[32];
    __shared__ float bs1[24];
    __shared__ float As2[2][8][256];               // producer tiles
    __shared__ float Bs2[2][8][64];

    int t = threadIdx.x, g = blockIdx.x;

    if (g >= GBLK) {
        // ================= GI producer path (blocks 128..143) =================
        int p = g - GBLK;
        int ar = t >> 1, aq = (t & 1) * 4;
        int rb = ar >> 5, rt = ar & 31;            // row -> (batch, token-in-chunk)
        int ty = t >> 4, tx = t & 15;              // micro-tile: 8 rows x 4 cols
        #pragma unroll 1
        for (int c = 0; c < 32; c++) {
            const float* xbase = xg + ((size_t)rb * TT + c * 32 + rt) * DD + aq;
            #pragma unroll 1
            for (int jj = 0; jj < 3; jj++) {
                int n0 = (p + jj * NPROD) * 64;
                unsigned long long acc[8][2];
                #pragma unroll
                for (int i = 0; i < 8; i++) { acc[i][0] = 0ull; acc[i][1] = 0ull; }
                {   // preload k-slab 0
                    float4 va = *(const float4*)(xbase);
                    As2[0][aq+0][ar]=va.x; As2[0][aq+1][ar]=va.y;
                    As2[0][aq+2][ar]=va.z; As2[0][aq+3][ar]=va.w;
                    if (t < 128) { int n = t >> 1; int q = (t & 1) * 4;
                        float4 vb = *(const float4*)(w_ih + (size_t)(n0+n)*DD + q);
                        Bs2[0][q+0][n]=vb.x; Bs2[0][q+1][n]=vb.y;
                        Bs2[0][q+2][n]=vb.z; Bs2[0][q+3][n]=vb.w; }
                }
                __syncthreads();
                #pragma unroll 1
                for (int kt = 0; kt < 128; kt++) {
                    int cb = kt & 1, nb = cb ^ 1;
                    if (kt + 1 < 128) {
                        int kofs = (kt + 1) << 3;
                        float4 va = *(const float4*)(xbase + kofs);
                        As2[nb][aq+0][ar]=va.x; As2[nb][aq+1][ar]=va.y;
                        As2[nb][aq+2][ar]=va.z; As2[nb][aq+3][ar]=va.w;
                        if (t < 128) { int n = t >> 1; int q = (t & 1) * 4;
                            float4 vb = *(const float4*)(w_ih + (size_t)(n0+n)*DD + kofs + q);
                            Bs2[nb][q+0][n]=vb.x; Bs2[nb][q+1][n]=vb.y;
                            Bs2[nb][q+2][n]=vb.z; Bs2[nb][q+3][n]=vb.w; }
                    }
                    #pragma unroll
                    for (int kk = 0; kk < 8; kk++) {
                        float4 a0 = *(const float4*)&As2[cb][kk][ty * 8];
                        float4 a1 = *(const float4*)&As2[cb][kk][ty * 8 + 4];
                        ulonglong2 b01 = *(const ulonglong2*)&Bs2[cb][kk][tx * 4];
                        float av[8] = {a0.x,a0.y,a0.z,a0.w,a1.x,a1.y,a1.z,a1.w};
                        #pragma unroll
                        for (int i = 0; i < 8; i++) {
                            unsigned long long pa = pack2(av[i]);
                            fma2(acc[i][0], b01.x, pa, acc[i][0]);
                            fma2(acc[i][1], b01.y, pa, acc[i][1]);
                        }
                    }
                    __syncthreads();
                }
                int col = n0 + tx * 4;
                float4 bv = *(const float4*)&b_ih[col];
                #pragma unroll
                for (int i = 0; i < 8; i++) {
                    int m = ty * 8 + i;
                    float4 v;
                    unpack2(acc[i][0], v.x, v.y);
                    unpack2(acc[i][1], v.z, v.w);
                    v.x += bv.x; v.y += bv.y; v.z += bv.z; v.w += bv.w;
                    *(float4*)&g_GI[((size_t)(m >> 5) * TT + c * 32 + (m & 31)) * D3 + col] = v;
                }
                __syncthreads();
            }
            __threadfence();
            __syncthreads();
            if (t == 0) atomicAdd(&g_giProg[c], 1u);
        }
        return;
    }

    // ================= recurrence path (blocks 0..127; R14 configuration) =================
    int d0 = g * 8;
    int w = t >> 5, lane = t & 31;

    int rsub = lane >> 2, kq1 = lane & 3;   // phase1 matvec roles
    int rg2 = lane >> 3, kq2 = lane & 7;    // phase2 matvec roles
    int te = t - 448;                       // elementwise roles (t >= 448)
    int ed = te >> 3, eb = te & 7;
    int dg = d0 + (ed & 7);

    // ---- weights resident in registers ----
    float w1[3][16];
    #pragma unroll
    for (int q = 0; q < 3; q++) {
        int rho = rsub * 3 + q;
        const float* wr = w_hh + (size_t)((rho >> 3) * DD + d0 + (rho & 7)) * DD
                        + w * 64 + kq1;
        #pragma unroll
        for (int i = 0; i < 16; i++) w1[q][i] = wr[4 * i];
    }
    float w2[2][8];
    #pragma unroll
    for (int r = 0; r < 2; r++) {
        const float* wr = gate_w + (size_t)(d0 + rg2 * 2 + r) * (2 * DD)
                        + w * 64 + kq2;
        #pragma unroll
        for (int i = 0; i < 8; i++) w2[r][i] = wr[8 * i];
    }
    if (t < 24) bs1[t] = b_hh[(t >> 3) * DD + d0 + (t & 7)];
    __syncthreads();

    unsigned e = 0;
    float h_own = 0.f, h1_own = 0.f;

    const ulonglong2* Hg  = (const ulonglong2*)g_Ht;
    const ulonglong2* H1g = (const ulonglong2*)g_H1t;

    // per-token operands, prefetched one token ahead
    float girC = 0, gizC = 0, ginC = 0, avC = 0, agvC = 0;
    float girN = 0, gizN = 0, ginN = 0, avN = 0, agvN = 0;
    if (t >= 448) {
        size_t ab = ((size_t)(eb * TT)) * DD + dg;
        avC = __ldg(&g_A[ab]); agvC = __ldg(&g_AG[ab]);
        wait_gi(0);
        size_t gb = ((size_t)(eb * TT)) * D3 + dg;
        girC = __ldcg(&g_GI[gb]); gizC = __ldcg(&g_GI[gb + DD]); ginC = __ldcg(&g_GI[gb + 2 * DD]);
    }

    for (int tok = 0; tok < TT; tok++) {
        #pragma unroll 1
        for (int s = 0; s < 4; s++) {
            // ---- phase 1: gh = W_hh . h ----
            {
                wait_tags8(g_tagH, w, e);
                unsigned long long acc[12];
                #pragma unroll
                for (int j = 0; j < 12; j++) acc[j] = 0ull;
                int kb = w * 64 + kq1;
                #pragma unroll
                for (int i = 0; i < 16; i++) {
                    int ii = (i + g) & 15;                 // block-staggered order
                    int k = kb + 4 * ii;
                    ulonglong2 p0 = __ldcg(&Hg[k * 2]);
                    ulonglong2 p1 = __ldcg(&Hg[k * 2 + 1]);
                    #pragma unroll
                    for (int q = 0; q < 3; q++) {
                        unsigned long long wd = pack2(w1[q][ii]);
                        fma2(acc[q*4+0], p0.x, wd, acc[q*4+0]);
                        fma2(acc[q*4+1], p0.y, wd, acc[q*4+1]);
                        fma2(acc[q*4+2], p1.x, wd, acc[q*4+2]);
                        fma2(acc[q*4+3], p1.y, wd, acc[q*4+3]);
                    }
                }
                #pragma unroll
                for (int o = 1; o <= 2; o <<= 1)
                    #pragma unroll
                    for (int j = 0; j < 12; j++)
                        acc[j] = add2(acc[j], __shfl_xor_sync(0xffffffffu, acc[j], o));
                if (kq1 == 0) {
                    #pragma unroll
                    for (int j = 0; j < 12; j++) part[w * 96 + rsub * 12 + j] = acc[j];
                }
            }
            __syncthreads();
            if (t >= 416) {                                // warps 13-15 reduce
                int tr = t - 416;
                unsigned long long d = part[tr];
                #pragma unroll
                for (int wv = 1; wv < 16; wv++) d = add2(d, part[wv * 96 + tr]);
                ghs[tr] = d;
            }
            __syncthreads();

            // ---- GRU elementwise -> publish h1 (top warps) ----
            if (t >= 448) {
                const float* ghf = (const float*)ghs;
                float gh[3];
                #pragma unroll
                for (int c = 0; c < 3; c++) {
                    int rho = c * 8 + ed;
                    int o = (rho / 3) * 12 + (rho % 3) * 4 + (eb >> 1);
                    gh[c] = ghf[o * 2 + (eb & 1)] + bs1[rho];
                }
                float rr = fsig(girC + gh[0]);
                float zz = fsig(gizC + gh[1]);
                float nn = ftanh(ginC + rr * gh[2]);
                h1_own = (1.f - zz) * nn + zz * h_own;
                __stcg(&g_H1t[dg * 8 + eb], h1_own);
                __syncwarp();
                if (lane == 0) {
                    unsigned tg = e + 1;
                    asm volatile("st.release.gpu.u32 [%0], %1;"
                                 :: "l"(&g_tagH1[(g * 2 + (w - 14)) * 8]), "r"(tg) : "memory");
                }
                // prefetch next token's operands (off the critical path)
                if (s == 0 && tok + 1 < TT) {
                    size_t ab = ((size_t)(eb * TT + tok + 1)) * DD + dg;
                    avN = __ldg(&g_A[ab]); agvN = __ldg(&g_AG[ab]);
                    wait_gi((tok + 1) >> 5);
                    size_t gb = ((size_t)(eb * TT + tok + 1)) * D3 + dg;
                    girN = __ldcg(&g_GI[gb]); gizN = __ldcg(&g_GI[gb + DD]);
                    ginN = __ldcg(&g_GI[gb + 2 * DD]);
                }
            }

            // ---- phase 2: gate dot ----
            {
                wait_tags8(g_tagH1, w, e + 1);
                unsigned long long a2[8];
                #pragma unroll
                for (int j = 0; j < 8; j++) a2[j] = 0ull;
                int kb = w * 64 + kq2;
                #pragma unroll
                for (int i = 0; i < 8; i++) {
                    int ii = (i + g) & 7;                  // block-staggered order
                    int k = kb + 8 * ii;
                    ulonglong2 p0 = __ldcg(&H1g[k * 2]);
                    ulonglong2 p1 = __ldcg(&H1g[k * 2 + 1]);
                    #pragma unroll
                    for (int r = 0; r < 2; r++) {
                        unsigned long long wd = pack2(w2[r][ii]);
                        fma2(a2[r*4+0], p0.x, wd, a2[r*4+0]);
                        fma2(a2[r*4+1], p0.y, wd, a2[r*4+1]);
                        fma2(a2[r*4+2], p1.x, wd, a2[r*4+2]);
                        fma2(a2[r*4+3], p1.y, wd, a2[r*4+3]);
                    }
                }
                #pragma unroll
                for (int o = 1; o <= 4; o <<= 1)
                    #pragma unroll
                    for (int j = 0; j < 8; j++)
                        a2[j] = add2(a2[j], __shfl_xor_sync(0xffffffffu, a2[j], o));
                if (kq2 == 0) {
                    #pragma unroll
                    for (int j = 0; j < 8; j++) part[w * 32 + rg2 * 8 + j] = a2[j];
                }
            }
            __syncthreads();
            if (t >= 480) {                                // warp 15 reduces
                int tr = t - 480;
                unsigned long long d = part[tr];
                #pragma unroll
                for (int wv = 1; wv < 16; wv++) d = add2(d, part[wv * 32 + tr]);
                g2s[tr] = d;
            }
            __syncthreads();

            // ---- gate elementwise -> publish new h (+ output on last sub-step) ----
            if (t >= 448) {
                const float* g2f = (const float*)g2s;
                float dot = g2f[ed * 8 + eb];
                float gv  = fsig(dot + agvC);
                h_own = gv * h1_own + (1.f - gv) * avC;
                __stcg(&g_Ht[dg * 8 + eb], h_own);
                if (s == 3) out[((size_t)(eb * TT + tok)) * DD + dg] = h_own;
                __syncwarp();
                if (lane == 0) {
                    unsigned tg = e + 1;
                    asm volatile("st.release.gpu.u32 [%0], %1;"
                                 :: "l"(&g_tagH[(g * 2 + (w - 14)) * 8]), "r"(tg) : "memory");
                }
            }
            e++;
        }
        girC = girN; gizC = gizN; ginC = ginN; avC = avN; agvC = agvN;
    }
}

// ---------------- launch ----------------
extern "C" void kernel_launch(void* const* d_in, const int* in_sizes, int n_in,
                              void* d_out, int out_size)
{
    (void)in_sizes; (void)n_in; (void)out_size;
    const float* x   = (const float*)d_in[0];
    const float* ipw = (const float*)d_in[1];
    const float* ipb = (const float*)d_in[2];
    const float* opw = (const float*)d_in[3];
    const float* opb = (const float*)d_in[4];
    const float* wih = (const float*)d_in[5];
    const float* whh = (const float*)d_in[6];
    const float* bih = (const float*)d_in[7];
    const float* bhh = (const float*)d_in[8];
    const float* gw  = (const float*)d_in[9];
    const float* gb  = (const float*)d_in[10];
    float* out = (float*)d_out;

    float *qkv, *S, *ctx, *A, *AG;
    cudaGetSymbolAddress((void**)&qkv, g_qkv);
    cudaGetSymbolAddress((void**)&S,   g_S);
    cudaGetSymbolAddress((void**)&ctx, g_ctx);
    cudaGetSymbolAddress((void**)&A,   g_A);
    cudaGetSymbolAddress((void**)&AG,  g_AG);

    dim3 blk(256);
    // 1) qkv = x @ in_proj^T + b            [8192,3072]
    gemm_k<128,true><<<dim3(D3/128, (BB*TT)/128, 1), blk>>>(
        x, DD, 0, 0, ipw, DD, 0, 0, qkv, D3, 0, 0, DD, 1, ipb, 1.f);
    // 2) scores S[b,h] = Q K^T / 8          batched 128x [1024,1024], K=64
    gemm_k<128,true><<<dim3(TT/128, TT/128, BB*HH), blk>>>(
        qkv,      D3, (long long)TT*D3, 64,
        qkv + DD, D3, (long long)TT*D3, 64,
        S, TT, (long long)HH*TT*TT, (long long)TT*TT,
        64, HH, nullptr, 0.125f);
    // 3) softmax rows
    softmax_k<<<BB*HH*TT, 256>>>(S);
    // 4) ctx[b,h] = S @ V                   batched 128x [1024,64], K=1024
    gemm_k<64,false><<<dim3(1, TT/128, BB*HH), blk>>>(
        S, TT, (long long)HH*TT*TT, (long long)TT*TT,
        qkv + 2*DD, D3, (long long)TT*D3, 64,
        ctx, DD, (long long)TT*DD, 64,
        TT, HH, nullptr, 1.f);
    // 5) A = ctx @ out_proj^T + b           [8192,1024]
    gemm_k<128,true><<<dim3(DD/128, (BB*TT)/128, 1), blk>>>(
        ctx, DD, 0, 0, opw, DD, 0, 0, A, DD, 0, 0, DD, 1, opb, 1.f);
    // 6) AG = A @ gate_w[:,D:]^T + gate_b   [8192,1024]
    gemm_k<128,true><<<dim3(DD/128, (BB*TT)/128, 1), blk>>>(
        A, DD, 0, 0, gw + DD, 2*DD, 0, 0, AG, DD, 0, 0, DD, 1, gb, 1.f);
    // 7) reset h buffers + tags + GI progress (deterministic across graph replays)
    reset_k<<<32, 256>>>();
    // 8) fused: recurrence (128 blocks) + in-flight GI producer (16 blocks)
    recur_k<<<GBLK + NPROD, PTH>>>(whh, bhh, gw, x, wih, bih, out);
}